// round 2
// baseline (speedup 1.0000x reference)
#include <cuda_runtime.h>
#include <cuda_bf16.h>
#include <math.h>

// Problem constants (from setup_inputs)
#define NMAX   50000
#define EMAX   800000
#define ETOT   (NMAX + EMAX)   // edges incl. self loops
#define HDIM   256
#define NEG_SLOPE 0.2f
#define EPS    1e-16f

// ---------------- scratch (no allocs allowed) ----------------
__device__ float g_bufA[(size_t)NMAX * HDIM];   // GEMM outputs (h = x@W)
__device__ float g_bufB[(size_t)NMAX * HDIM];   // aggregation outputs
__device__ float g_asrc[NMAX];
__device__ float g_adst[NMAX];
__device__ float g_gate[NMAX];
__device__ int   g_counts[NMAX];
__device__ int   g_fill[NMAX];
__device__ int   g_rowptr[NMAX + 1];
__device__ int   g_csrc[ETOT];
__device__ float g_stats[2];
__device__ float g_partial[256 * 256];

// ---------------- CSR build ----------------
__global__ void k_init_counts(int N) {
    int i = blockIdx.x * blockDim.x + threadIdx.x;
    if (i < N) { g_counts[i] = 1; g_fill[i] = 0; }   // 1 = self loop
}

__global__ void k_hist(const int* __restrict__ ei, int E) {
    int e = blockIdx.x * blockDim.x + threadIdx.x;
    if (e < E) {
        int d = ei[E + e];
        atomicAdd(&g_counts[d], 1);
    }
}

// single block, 1024 threads: exclusive scan over N counts -> rowptr
__global__ void k_scan(int N) {
    __shared__ int ssum[1024];
    int t = threadIdx.x;
    int chunk = (N + 1023) / 1024;
    int start = t * chunk;
    int end = min(start + chunk, N);
    int s = 0;
    for (int i = start; i < end; i++) s += g_counts[i];
    ssum[t] = s;
    __syncthreads();
    for (int off = 1; off < 1024; off <<= 1) {
        int v = ssum[t];
        int add = (t >= off) ? ssum[t - off] : 0;
        __syncthreads();
        ssum[t] = v + add;
        __syncthreads();
    }
    int run = (t == 0) ? 0 : ssum[t - 1];
    for (int i = start; i < end; i++) { g_rowptr[i] = run; run += g_counts[i]; }
    if (t == 1023) g_rowptr[N] = run;
}

__global__ void k_scatter(const int* __restrict__ ei, int N, int E) {
    int i = blockIdx.x * blockDim.x + threadIdx.x;
    if (i >= N + E) return;
    int s, d;
    if (i < N) { s = i; d = i; }
    else {
        int e = i - N;
        s = ei[e];
        d = ei[E + e];
    }
    int pos = g_rowptr[d] + atomicAdd(&g_fill[d], 1);
    g_csrc[pos] = s;
}

// ---------------- fp32 GEMM: C[M][256] = A[M][K] @ B[K][256] ----------------
// 64x64 tile, 256 threads, 4x4 micro-tile, BK=16
__global__ void k_gemm(const float* __restrict__ A, const float* __restrict__ B,
                       float* __restrict__ C, int M, int K) {
    __shared__ float As[16][64];
    __shared__ float Bs[16][64];
    int tid = threadIdx.x;
    int ty = tid >> 4, tx = tid & 15;
    int m0 = blockIdx.x * 64, n0 = blockIdx.y * 64;
    int ar = tid >> 2, ac = (tid & 3) * 4;   // A: row 0..63, col-group
    int br = tid >> 4, bc = (tid & 15) * 4;  // B: k-row 0..15, col-group
    float c[4][4] = {};
    for (int k0 = 0; k0 < K; k0 += 16) {
        int gm = m0 + ar;
        float4 av = make_float4(0.f, 0.f, 0.f, 0.f);
        if (gm < M) av = *(const float4*)(A + (size_t)gm * K + k0 + ac);
        float4 bv = *(const float4*)(B + (size_t)(k0 + br) * HDIM + n0 + bc);
        As[ac + 0][ar] = av.x;
        As[ac + 1][ar] = av.y;
        As[ac + 2][ar] = av.z;
        As[ac + 3][ar] = av.w;
        *(float4*)&Bs[br][bc] = bv;
        __syncthreads();
#pragma unroll
        for (int kk = 0; kk < 16; kk++) {
            float4 a = *(float4*)&As[kk][ty * 4];
            float4 b = *(float4*)&Bs[kk][tx * 4];
            c[0][0] += a.x * b.x; c[0][1] += a.x * b.y; c[0][2] += a.x * b.z; c[0][3] += a.x * b.w;
            c[1][0] += a.y * b.x; c[1][1] += a.y * b.y; c[1][2] += a.y * b.z; c[1][3] += a.y * b.w;
            c[2][0] += a.z * b.x; c[2][1] += a.z * b.y; c[2][2] += a.z * b.z; c[2][3] += a.z * b.w;
            c[3][0] += a.w * b.x; c[3][1] += a.w * b.y; c[3][2] += a.w * b.z; c[3][3] += a.w * b.w;
        }
        __syncthreads();
    }
#pragma unroll
    for (int i = 0; i < 4; i++) {
        int gm = m0 + ty * 4 + i;
        if (gm < M)
            *(float4*)(C + (size_t)gm * HDIM + n0 + tx * 4) =
                make_float4(c[i][0], c[i][1], c[i][2], c[i][3]);
    }
}

// ---------------- per-node attention scalars: a_src[n], a_dst[n] ----------------
__global__ void k_attvec(const float* __restrict__ h, const float* __restrict__ vs,
                         const float* __restrict__ vd) {
    int n = blockIdx.x, t = threadIdx.x;
    __shared__ float r1[256], r2[256];
    float v = h[(size_t)n * HDIM + t];
    r1[t] = v * vs[t];
    r2[t] = v * vd[t];
    __syncthreads();
    for (int off = 128; off > 0; off >>= 1) {
        if (t < off) { r1[t] += r1[t + off]; r2[t] += r2[t + off]; }
        __syncthreads();
    }
    if (t == 0) { g_asrc[n] = r1[0]; g_adst[n] = r2[0]; }
}

// ---------------- edge softmax + aggregation (one block per dst) ----------------
__global__ void k_agg(const float* __restrict__ hin, const float* __restrict__ bias,
                      float* __restrict__ hout) {
    int n = blockIdx.x, t = threadIdx.x;
    int begin = g_rowptr[n], end = g_rowptr[n + 1];
    float ad = g_adst[n];
    __shared__ float sw[256];
    __shared__ int   ss[256];
    __shared__ float red[256];

    // pass 1: segment max of leaky_relu(a_src[s] + a_dst[n])
    float m = -1e30f;
    for (int e = begin + t; e < end; e += 256) {
        float v = g_asrc[g_csrc[e]] + ad;
        v = v > 0.f ? v : NEG_SLOPE * v;
        m = fmaxf(m, v);
    }
    red[t] = m; __syncthreads();
    for (int off = 128; off > 0; off >>= 1) {
        if (t < off) red[t] = fmaxf(red[t], red[t + off]);
        __syncthreads();
    }
    m = red[0];
    __syncthreads();

    // pass 2: weights + weighted gather of h[src]
    float acc = 0.f, lsum = 0.f;
    for (int cs = begin; cs < end; cs += 256) {
        int cnt = min(256, end - cs);
        if (t < cnt) {
            int s = g_csrc[cs + t];
            float v = g_asrc[s] + ad;
            v = v > 0.f ? v : NEG_SLOPE * v;
            float w = expf(v - m);
            sw[t] = w; ss[t] = s; lsum += w;
        }
        __syncthreads();
        for (int j = 0; j < cnt; j++)
            acc += sw[j] * hin[(size_t)ss[j] * HDIM + t];
        __syncthreads();
    }
    red[t] = lsum; __syncthreads();
    for (int off = 128; off > 0; off >>= 1) {
        if (t < off) red[t] += red[t + off];
        __syncthreads();
    }
    float S = red[0];
    float o = acc / (S + EPS) + bias[t];
    hout[(size_t)n * HDIM + t] = fmaxf(o, 0.f);   // relu after each layer
}

// ---------------- global attention ----------------
__global__ void k_gate(const float* __restrict__ h, const float* __restrict__ gw,
                       const float* __restrict__ gb) {
    int n = blockIdx.x, t = threadIdx.x;
    __shared__ float r[256];
    r[t] = h[(size_t)n * HDIM + t] * gw[t];
    __syncthreads();
    for (int off = 128; off > 0; off >>= 1) {
        if (t < off) r[t] += r[t + off];
        __syncthreads();
    }
    if (t == 0) g_gate[n] = r[0] + gb[0];
}

__global__ void k_softmax_stats(int N) {
    __shared__ float red[1024];
    int t = threadIdx.x;
    float m = -1e30f;
    for (int i = t; i < N; i += 1024) m = fmaxf(m, g_gate[i]);
    red[t] = m; __syncthreads();
    for (int off = 512; off > 0; off >>= 1) {
        if (t < off) red[t] = fmaxf(red[t], red[t + off]);
        __syncthreads();
    }
    m = red[0];
    __syncthreads();
    float s = 0.f;
    for (int i = t; i < N; i += 1024) s += expf(g_gate[i] - m);
    red[t] = s; __syncthreads();
    for (int off = 512; off > 0; off >>= 1) {
        if (t < off) red[t] += red[t + off];
        __syncthreads();
    }
    if (t == 0) { g_stats[0] = m; g_stats[1] = red[0]; }
}

__global__ void k_ga_partial(const float* __restrict__ h, int N) {
    int b = blockIdx.x, t = threadIdx.x;
    float m = g_stats[0], S = g_stats[1];
    float acc = 0.f;
    for (int n = b; n < N; n += 256)
        acc += (expf(g_gate[n] - m) / S) * h[(size_t)n * HDIM + t];
    g_partial[b * 256 + t] = acc;
}

__global__ void k_ga_final(float* __restrict__ out) {
    int t = threadIdx.x;
    float acc = 0.f;
    for (int b = 0; b < 256; b++) acc += g_partial[b * 256 + t];
    out[t] = acc;
}

// ---------------- launch ----------------
extern "C" void kernel_launch(void* const* d_in, const int* in_sizes, int n_in,
                              void* d_out, int out_size) {
    const float* x   = (const float*)d_in[0];
    const int*   ei  = (const int*)d_in[1];     // int32! (JAX x64 disabled)
    const float* W1  = (const float*)d_in[2];
    const float* b1  = (const float*)d_in[3];
    const float* as1 = (const float*)d_in[4];
    const float* ad1 = (const float*)d_in[5];
    const float* W2  = (const float*)d_in[6];
    const float* b2  = (const float*)d_in[7];
    const float* as2 = (const float*)d_in[8];
    const float* ad2 = (const float*)d_in[9];
    const float* gw  = (const float*)d_in[10];
    const float* gb  = (const float*)d_in[11];
    float*       out = (float*)d_out;

    const int D = 768;
    const int N = in_sizes[0] / D;       // 50000
    const int E = in_sizes[1] / 2;       // 800000

    float *bufA, *bufB;
    cudaGetSymbolAddress((void**)&bufA, g_bufA);
    cudaGetSymbolAddress((void**)&bufB, g_bufB);

    // ---- CSR build (by dst, incl. self loops) ----
    k_init_counts<<<(N + 255) / 256, 256>>>(N);
    k_hist<<<(E + 255) / 256, 256>>>(ei, E);
    k_scan<<<1, 1024>>>(N);
    k_scatter<<<(N + E + 255) / 256, 256>>>(ei, N, E);

    dim3 g1((N + 63) / 64, HDIM / 64);

    // ---- layer 1 ----
    k_gemm<<<g1, 256>>>(x, W1, bufA, N, D);
    k_attvec<<<N, 256>>>(bufA, as1, ad1);
    k_agg<<<N, 256>>>(bufA, b1, bufB);

    // ---- layer 2 ----
    k_gemm<<<g1, 256>>>(bufB, W2, bufA, N, HDIM);
    k_attvec<<<N, 256>>>(bufA, as2, ad2);
    k_agg<<<N, 256>>>(bufA, b2, bufB);

    // ---- global attention ----
    k_gate<<<N, 256>>>(bufB, gw, gb);
    k_softmax_stats<<<1, 1024>>>(N);
    k_ga_partial<<<256, 256>>>(bufB, N);
    k_ga_final<<<1, 256>>>(out);
}

// round 3
// speedup vs baseline: 1.0300x; 1.0300x over previous
#include <cuda_runtime.h>
#include <cuda_bf16.h>
#include <math.h>

#define NMAX   50000
#define EMAX   800000
#define ETOT   (NMAX + EMAX)
#define HDIM   256
#define NEG_SLOPE 0.2f
#define EPS    1e-16f

// ---------------- scratch ----------------
__device__ float g_bufA[(size_t)NMAX * HDIM];
__device__ float g_bufB[(size_t)NMAX * HDIM];
__device__ float g_asrc[NMAX];
__device__ float g_adst[NMAX];
__device__ float g_gate[NMAX];
__device__ int   g_counts[NMAX];
__device__ int   g_fill[NMAX];
__device__ int   g_rowptr[NMAX + 1];
__device__ int   g_csrc[ETOT];
__device__ float g_stats[2];
__device__ float g_partial[256 * 256];

// ---------------- CSR build ----------------
__global__ void k_init_counts(int N) {
    int i = blockIdx.x * blockDim.x + threadIdx.x;
    if (i < N) { g_counts[i] = 1; g_fill[i] = 0; }
}

__global__ void k_hist(const int* __restrict__ ei, int E) {
    int e = blockIdx.x * blockDim.x + threadIdx.x;
    if (e < E) atomicAdd(&g_counts[ei[E + e]], 1);
}

__global__ void k_scan(int N) {
    __shared__ int ssum[1024];
    int t = threadIdx.x;
    int chunk = (N + 1023) / 1024;
    int start = t * chunk;
    int end = min(start + chunk, N);
    int s = 0;
    for (int i = start; i < end; i++) s += g_counts[i];
    ssum[t] = s;
    __syncthreads();
    for (int off = 1; off < 1024; off <<= 1) {
        int v = ssum[t];
        int add = (t >= off) ? ssum[t - off] : 0;
        __syncthreads();
        ssum[t] = v + add;
        __syncthreads();
    }
    int run = (t == 0) ? 0 : ssum[t - 1];
    for (int i = start; i < end; i++) { g_rowptr[i] = run; run += g_counts[i]; }
    if (t == 1023) g_rowptr[N] = run;
}

__global__ void k_scatter(const int* __restrict__ ei, int N, int E) {
    int i = blockIdx.x * blockDim.x + threadIdx.x;
    if (i >= N + E) return;
    int s, d;
    if (i < N) { s = i; d = i; }
    else { s = ei[i - N]; d = ei[E + i - N]; }
    int pos = g_rowptr[d] + atomicAdd(&g_fill[d], 1);
    g_csrc[pos] = s;
}

// ---------------- TF32 tensor-core GEMM ----------------
// C[M][256] = A[M][K] @ B[K][256].  128x128 block tile, BK=32, 8 warps.
// Warp tile 64x32 (warps 2Mx4N).  m16n8k8 tf32 mma; smem in fragment order.
__device__ __forceinline__ unsigned f2tf32(float x) {
    unsigned r;
    asm("cvt.rna.tf32.f32 %0, %1;" : "=r"(r) : "f"(x));
    return r;
}

__global__ __launch_bounds__(256) void k_gemm_tf32(
        const float* __restrict__ A, const float* __restrict__ B,
        float* __restrict__ C, int M, int K) {
    // A: 8 mtiles x 4 ktiles x 128 (fragment order: lane*4 + reg)
    // B: 16 ntiles x 4 ktiles x 64 (fragment order: lane*2 + reg)
    __shared__ unsigned As[4096];
    __shared__ unsigned Bs[4096];
    int tid = threadIdx.x;
    int lane = tid & 31, warp = tid >> 5;
    int warp_m = warp >> 2, warp_n = warp & 3;
    int m0 = blockIdx.x * 128;
    int n0 = blockIdx.y * 128;
    float c[4][4][4];
#pragma unroll
    for (int i = 0; i < 4; i++)
#pragma unroll
        for (int j = 0; j < 4; j++)
#pragma unroll
            for (int r = 0; r < 4; r++) c[i][j][r] = 0.f;

    for (int k0 = 0; k0 < K; k0 += 32) {
        // ---- stage A tile (128 x 32) ----
#pragma unroll
        for (int i = 0; i < 4; i++) {
            int f = tid + i * 256;          // float4 index, 1024 total
            int m = f >> 3, kq = f & 7;
            float4 v = make_float4(0.f, 0.f, 0.f, 0.f);
            if (m0 + m < M) v = *(const float4*)(A + (size_t)(m0 + m) * K + k0 + kq * 4);
            int mt = m >> 4, lm = m & 15;
            float vv[4] = {v.x, v.y, v.z, v.w};
#pragma unroll
            for (int j = 0; j < 4; j++) {
                int k = kq * 4 + j;
                int kt = k >> 3, lk = k & 7;
                int ln = (lm & 7) * 4 + (lk & 3);
                int reg = (lm >> 3) | ((lk >> 2) << 1);
                As[(mt * 4 + kt) * 128 + ln * 4 + reg] = f2tf32(vv[j]);
            }
        }
        // ---- stage B tile (32 x 128) ----
#pragma unroll
        for (int i = 0; i < 4; i++) {
            int f = tid + i * 256;
            int k = f >> 5, nq = f & 31;
            float4 v = *(const float4*)(B + (size_t)(k0 + k) * HDIM + n0 + nq * 4);
            int kt = k >> 3, lk = k & 7;
            float vv[4] = {v.x, v.y, v.z, v.w};
#pragma unroll
            for (int j = 0; j < 4; j++) {
                int n = nq * 4 + j;
                int nt = n >> 3, ln = n & 7;
                Bs[(nt * 4 + kt) * 64 + (ln * 4 + (lk & 3)) * 2 + (lk >> 2)] = f2tf32(vv[j]);
            }
        }
        __syncthreads();
#pragma unroll
        for (int kt = 0; kt < 4; kt++) {
            unsigned a[4][4], b[4][2];
#pragma unroll
            for (int mi = 0; mi < 4; mi++) {
                const uint4* p = (const uint4*)&As[((warp_m * 4 + mi) * 4 + kt) * 128 + lane * 4];
                uint4 v = *p;
                a[mi][0] = v.x; a[mi][1] = v.y; a[mi][2] = v.z; a[mi][3] = v.w;
            }
#pragma unroll
            for (int ni = 0; ni < 4; ni++) {
                const uint2* p = (const uint2*)&Bs[((warp_n * 4 + ni) * 4 + kt) * 64 + lane * 2];
                uint2 v = *p;
                b[ni][0] = v.x; b[ni][1] = v.y;
            }
#pragma unroll
            for (int mi = 0; mi < 4; mi++)
#pragma unroll
                for (int ni = 0; ni < 4; ni++) {
                    asm volatile(
                        "mma.sync.aligned.m16n8k8.row.col.f32.tf32.tf32.f32 "
                        "{%0,%1,%2,%3}, {%4,%5,%6,%7}, {%8,%9}, {%0,%1,%2,%3};\n"
                        : "+f"(c[mi][ni][0]), "+f"(c[mi][ni][1]),
                          "+f"(c[mi][ni][2]), "+f"(c[mi][ni][3])
                        : "r"(a[mi][0]), "r"(a[mi][1]), "r"(a[mi][2]), "r"(a[mi][3]),
                          "r"(b[ni][0]), "r"(b[ni][1]));
                }
        }
        __syncthreads();
    }
    // ---- epilogue ----
    int g = lane >> 2, t = lane & 3;
#pragma unroll
    for (int mi = 0; mi < 4; mi++) {
#pragma unroll
        for (int ni = 0; ni < 4; ni++) {
            int m = m0 + warp_m * 64 + mi * 16 + g;
            int n = n0 + warp_n * 32 + ni * 8 + t * 2;
            if (m < M)
                *(float2*)(C + (size_t)m * HDIM + n) =
                    make_float2(c[mi][ni][0], c[mi][ni][1]);
            if (m + 8 < M)
                *(float2*)(C + (size_t)(m + 8) * HDIM + n) =
                    make_float2(c[mi][ni][2], c[mi][ni][3]);
        }
    }
}

// ---------------- per-node attention scalars ----------------
__global__ void k_attvec(const float* __restrict__ h, const float* __restrict__ vs,
                         const float* __restrict__ vd) {
    int n = blockIdx.x, t = threadIdx.x;
    __shared__ float r1[256], r2[256];
    float v = h[(size_t)n * HDIM + t];
    r1[t] = v * vs[t];
    r2[t] = v * vd[t];
    __syncthreads();
    for (int off = 128; off > 0; off >>= 1) {
        if (t < off) { r1[t] += r1[t + off]; r2[t] += r2[t + off]; }
        __syncthreads();
    }
    if (t == 0) { g_asrc[n] = r1[0]; g_adst[n] = r2[0]; }
}

// ---------------- edge softmax + aggregation ----------------
__global__ void k_agg(const float* __restrict__ hin, const float* __restrict__ bias,
                      float* __restrict__ hout) {
    int n = blockIdx.x, t = threadIdx.x;
    int begin = g_rowptr[n], end = g_rowptr[n + 1];
    float ad = g_adst[n];
    __shared__ float sw[256];
    __shared__ int   ss[256];
    __shared__ float red[256];

    float m = -1e30f;
    for (int e = begin + t; e < end; e += 256) {
        float v = g_asrc[g_csrc[e]] + ad;
        v = v > 0.f ? v : NEG_SLOPE * v;
        m = fmaxf(m, v);
    }
    red[t] = m; __syncthreads();
    for (int off = 128; off > 0; off >>= 1) {
        if (t < off) red[t] = fmaxf(red[t], red[t + off]);
        __syncthreads();
    }
    m = red[0];
    __syncthreads();

    float acc = 0.f, lsum = 0.f;
    for (int cs = begin; cs < end; cs += 256) {
        int cnt = min(256, end - cs);
        if (t < cnt) {
            int s = g_csrc[cs + t];
            float v = g_asrc[s] + ad;
            v = v > 0.f ? v : NEG_SLOPE * v;
            float w = expf(v - m);
            sw[t] = w; ss[t] = s; lsum += w;
        }
        __syncthreads();
        for (int j = 0; j < cnt; j++)
            acc += sw[j] * hin[(size_t)ss[j] * HDIM + t];
        __syncthreads();
    }
    red[t] = lsum; __syncthreads();
    for (int off = 128; off > 0; off >>= 1) {
        if (t < off) red[t] += red[t + off];
        __syncthreads();
    }
    float S = red[0];
    float o = acc / (S + EPS) + bias[t];
    hout[(size_t)n * HDIM + t] = fmaxf(o, 0.f);
}

// ---------------- global attention ----------------
__global__ void k_gate(const float* __restrict__ h, const float* __restrict__ gw,
                       const float* __restrict__ gb) {
    int n = blockIdx.x, t = threadIdx.x;
    __shared__ float r[256];
    r[t] = h[(size_t)n * HDIM + t] * gw[t];
    __syncthreads();
    for (int off = 128; off > 0; off >>= 1) {
        if (t < off) r[t] += r[t + off];
        __syncthreads();
    }
    if (t == 0) g_gate[n] = r[0] + gb[0];
}

__global__ void k_softmax_stats(int N) {
    __shared__ float red[1024];
    int t = threadIdx.x;
    float m = -1e30f;
    for (int i = t; i < N; i += 1024) m = fmaxf(m, g_gate[i]);
    red[t] = m; __syncthreads();
    for (int off = 512; off > 0; off >>= 1) {
        if (t < off) red[t] = fmaxf(red[t], red[t + off]);
        __syncthreads();
    }
    m = red[0];
    __syncthreads();
    float s = 0.f;
    for (int i = t; i < N; i += 1024) s += expf(g_gate[i] - m);
    red[t] = s; __syncthreads();
    for (int off = 512; off > 0; off >>= 1) {
        if (t < off) red[t] += red[t + off];
        __syncthreads();
    }
    if (t == 0) { g_stats[0] = m; g_stats[1] = red[0]; }
}

__global__ void k_ga_partial(const float* __restrict__ h, int N) {
    int b = blockIdx.x, t = threadIdx.x;
    float m = g_stats[0], S = g_stats[1];
    float acc = 0.f;
    for (int n = b; n < N; n += 256)
        acc += (expf(g_gate[n] - m) / S) * h[(size_t)n * HDIM + t];
    g_partial[b * 256 + t] = acc;
}

__global__ void k_ga_final(float* __restrict__ out) {
    int t = threadIdx.x;
    float acc = 0.f;
    for (int b = 0; b < 256; b++) acc += g_partial[b * 256 + t];
    out[t] = acc;
}

// ---------------- launch ----------------
extern "C" void kernel_launch(void* const* d_in, const int* in_sizes, int n_in,
                              void* d_out, int out_size) {
    const float* x   = (const float*)d_in[0];
    const int*   ei  = (const int*)d_in[1];
    const float* W1  = (const float*)d_in[2];
    const float* b1  = (const float*)d_in[3];
    const float* as1 = (const float*)d_in[4];
    const float* ad1 = (const float*)d_in[5];
    const float* W2  = (const float*)d_in[6];
    const float* b2  = (const float*)d_in[7];
    const float* as2 = (const float*)d_in[8];
    const float* ad2 = (const float*)d_in[9];
    const float* gw  = (const float*)d_in[10];
    const float* gb  = (const float*)d_in[11];
    float*       out = (float*)d_out;

    const int D = 768;
    const int N = in_sizes[0] / D;
    const int E = in_sizes[1] / 2;

    float *bufA, *bufB;
    cudaGetSymbolAddress((void**)&bufA, g_bufA);
    cudaGetSymbolAddress((void**)&bufB, g_bufB);

    // CSR build
    k_init_counts<<<(N + 255) / 256, 256>>>(N);
    k_hist<<<(E + 255) / 256, 256>>>(ei, E);
    k_scan<<<1, 1024>>>(N);
    k_scatter<<<(N + E + 255) / 256, 256>>>(ei, N, E);

    dim3 gg((N + 127) / 128, HDIM / 128);

    // layer 1
    k_gemm_tf32<<<gg, 256>>>(x, W1, bufA, N, D);
    k_attvec<<<N, 256>>>(bufA, as1, ad1);
    k_agg<<<N, 256>>>(bufA, b1, bufB);

    // layer 2
    k_gemm_tf32<<<gg, 256>>>(bufB, W2, bufA, N, HDIM);
    k_attvec<<<N, 256>>>(bufA, as2, ad2);
    k_agg<<<N, 256>>>(bufA, b2, bufB);

    // global attention
    k_gate<<<N, 256>>>(bufB, gw, gb);
    k_softmax_stats<<<1, 1024>>>(N);
    k_ga_partial<<<256, 256>>>(bufB, N);
    k_ga_final<<<1, 256>>>(out);
}

// round 6
// speedup vs baseline: 1.4411x; 1.3992x over previous
#include <cuda_runtime.h>
#include <cuda_bf16.h>
#include <math.h>
#include <stdint.h>

#define NMAX   50000
#define EMAX   800000
#define ETOT   (NMAX + EMAX)
#define HDIM   256
#define NEG_SLOPE 0.2f
#define EPS    1e-16f

// ---------------- scratch ----------------
__device__ float g_bufA[(size_t)NMAX * HDIM];
__device__ float g_bufB[(size_t)NMAX * HDIM];
__device__ float g_WT[768 * HDIM];          // transposed weights [N][K]
__device__ float g_asrc[NMAX];
__device__ float g_adst[NMAX];
__device__ float g_gate[NMAX];
__device__ int   g_counts[NMAX];
__device__ int   g_fill[NMAX];
__device__ int   g_rowptr[NMAX + 1];
__device__ int   g_csrc[ETOT];
__device__ float g_stats[2];
__device__ float g_partial[256 * 256];

// ---------------- helpers ----------------
__device__ __forceinline__ uint32_t s2u(const void* p) {
    uint32_t a;
    asm("{ .reg .u64 t; cvta.to.shared.u64 t, %1; cvt.u32.u64 %0, t; }" : "=r"(a) : "l"(p));
    return a;
}
__device__ __forceinline__ uint32_t b2u(__nv_bfloat16 a, __nv_bfloat16 b) {
    uint16_t ua = *(uint16_t*)&a, ub = *(uint16_t*)&b;
    return (uint32_t)ua | ((uint32_t)ub << 16);
}
// 8 fp32 -> 8 bf16 hi + 8 bf16 lo (error split)
__device__ __forceinline__ void cvt8(float4 v0, float4 v1, uint4& hi, uint4& lo) {
    float f[8] = {v0.x, v0.y, v0.z, v0.w, v1.x, v1.y, v1.z, v1.w};
    uint32_t h[4], l[4];
#pragma unroll
    for (int i = 0; i < 4; i++) {
        __nv_bfloat16 ha = __float2bfloat16_rn(f[2 * i]);
        __nv_bfloat16 hb = __float2bfloat16_rn(f[2 * i + 1]);
        float ra = f[2 * i] - __bfloat162float(ha);
        float rb = f[2 * i + 1] - __bfloat162float(hb);
        h[i] = b2u(ha, hb);
        l[i] = b2u(__float2bfloat16_rn(ra), __float2bfloat16_rn(rb));
    }
    hi = make_uint4(h[0], h[1], h[2], h[3]);
    lo = make_uint4(l[0], l[1], l[2], l[3]);
}
__device__ __forceinline__ void ldsm4(uint32_t& r0, uint32_t& r1, uint32_t& r2,
                                      uint32_t& r3, uint32_t addr) {
    asm volatile("ldmatrix.sync.aligned.m8n8.x4.shared.b16 {%0,%1,%2,%3}, [%4];"
                 : "=r"(r0), "=r"(r1), "=r"(r2), "=r"(r3) : "r"(addr));
}
#define MMA_BF16(c, a, b) \
    asm volatile("mma.sync.aligned.m16n8k16.row.col.f32.bf16.bf16.f32 " \
        "{%0,%1,%2,%3}, {%4,%5,%6,%7}, {%8,%9}, {%0,%1,%2,%3};" \
        : "+f"((c)[0]), "+f"((c)[1]), "+f"((c)[2]), "+f"((c)[3]) \
        : "r"((a)[0]), "r"((a)[1]), "r"((a)[2]), "r"((a)[3]), \
          "r"((b)[0]), "r"((b)[1]))

// ---------------- CSR build ----------------
__global__ void k_init_counts(int N) {
    int i = blockIdx.x * blockDim.x + threadIdx.x;
    if (i < N) { g_counts[i] = 1; g_fill[i] = 0; }
}
__global__ void k_hist(const int* __restrict__ ei, int E) {
    int e = blockIdx.x * blockDim.x + threadIdx.x;
    if (e < E) atomicAdd(&g_counts[ei[E + e]], 1);
}
__global__ void k_scan(int N) {
    __shared__ int ssum[1024];
    int t = threadIdx.x;
    int chunk = (N + 1023) / 1024;
    int start = t * chunk, end = min(start + chunk, N);
    int s = 0;
    for (int i = start; i < end; i++) s += g_counts[i];
    ssum[t] = s;
    __syncthreads();
    for (int off = 1; off < 1024; off <<= 1) {
        int v = ssum[t];
        int add = (t >= off) ? ssum[t - off] : 0;
        __syncthreads();
        ssum[t] = v + add;
        __syncthreads();
    }
    int run = (t == 0) ? 0 : ssum[t - 1];
    for (int i = start; i < end; i++) { g_rowptr[i] = run; run += g_counts[i]; }
    if (t == 1023) g_rowptr[N] = run;
}
__global__ void k_scatter(const int* __restrict__ ei, int N, int E) {
    int i = blockIdx.x * blockDim.x + threadIdx.x;
    if (i >= N + E) return;
    int s, d;
    if (i < N) { s = i; d = i; }
    else { s = ei[i - N]; d = ei[E + i - N]; }
    int pos = g_rowptr[d] + atomicAdd(&g_fill[d], 1);
    g_csrc[pos] = s;
}

// ---------------- weight transpose: WT[n][k] = W[k][n] ----------------
__global__ void k_transpose(const float* __restrict__ W, float* __restrict__ WT,
                            int K, int N) {
    __shared__ float t[32][33];
    int bx = blockIdx.x * 32, by = blockIdx.y * 32;
    int tx = threadIdx.x, ty = threadIdx.y;
#pragma unroll
    for (int j = 0; j < 4; j++) {
        int k = by + ty + j * 8;
        if (k < K && bx + tx < N) t[ty + j * 8][tx] = W[(size_t)k * N + bx + tx];
    }
    __syncthreads();
#pragma unroll
    for (int j = 0; j < 4; j++) {
        int n = bx + ty + j * 8;
        int k = by + tx;
        if (n < N && k < K) WT[(size_t)n * K + k] = t[tx][ty + j * 8];
    }
}

// ---------------- 3xBF16 tensor-core GEMM ----------------
// C[M][256] = A[M][K] @ WT^T (WT is [256][K] K-major).
// Block tile 128x128 (grid.y=2 over N), BK=32, 8 warps (64x32 warp tiles).
// Smem rows padded to 80B (stride 5x16B, gcd(5,8)=1 => ldmatrix conflict-free).
#define ROWB 80
#define OFF_AH 0
#define OFF_AL 10240
#define OFF_BH 20480
#define OFF_BL 30720

__global__ __launch_bounds__(256) void k_gemm_bf16(
        const float* __restrict__ A, const float* __restrict__ WT,
        float* __restrict__ C, int M, int K) {
    __shared__ __align__(16) uint8_t sm[40960];
    uint32_t sb = s2u(sm);
    int tid = threadIdx.x;
    int lane = tid & 31, wid = tid >> 5;
    int warp_m = wid >> 2, warp_n = wid & 3;
    int m0 = blockIdx.x * 128, n0 = blockIdx.y * 128;
    int rowsValid = M - m0;

    float c[4][4][4];
#pragma unroll
    for (int i = 0; i < 4; i++)
#pragma unroll
        for (int j = 0; j < 4; j++)
#pragma unroll
            for (int r = 0; r < 4; r++) c[i][j][r] = 0.f;

    // ldmatrix lane->address bases
    int r16 = lane & 15, cblk = lane >> 4;               // A: row in 16-tile, k 8-block
    uint32_t aBase = (uint32_t)(warp_m * 64 + r16) * ROWB + cblk * 16;
    uint32_t bn = (lane & 7) + ((lane >> 4) << 3);       // B: n within 16-group
    uint32_t bkb = (lane >> 3) & 1;                      // B: k 8-block
    uint32_t bBase = (uint32_t)(warp_n * 32 + bn) * ROWB + bkb * 16;

    for (int k0 = 0; k0 < K; k0 += 32) {
        // ---- stage A (128 x 32) hi/lo ----
#pragma unroll
        for (int i = 0; i < 2; i++) {
            int u = tid + i * 256;
            int m = u >> 2, kq = u & 3;
            float4 v0 = make_float4(0.f, 0.f, 0.f, 0.f), v1 = v0;
            if (m < rowsValid) {
                const float* p = A + (size_t)(m0 + m) * K + k0 + kq * 8;
                v0 = *(const float4*)p;
                v1 = *(const float4*)(p + 4);
            }
            uint4 hi, lo;
            cvt8(v0, v1, hi, lo);
            *(uint4*)(sm + OFF_AH + m * ROWB + kq * 16) = hi;
            *(uint4*)(sm + OFF_AL + m * ROWB + kq * 16) = lo;
        }
        // ---- stage B (128n x 32k) hi/lo ----
#pragma unroll
        for (int i = 0; i < 2; i++) {
            int u = tid + i * 256;
            int nl = u >> 2, kq = u & 3;
            const float* p = WT + (size_t)(n0 + nl) * K + k0 + kq * 8;
            float4 v0 = *(const float4*)p;
            float4 v1 = *(const float4*)(p + 4);
            uint4 hi, lo;
            cvt8(v0, v1, hi, lo);
            *(uint4*)(sm + OFF_BH + nl * ROWB + kq * 16) = hi;
            *(uint4*)(sm + OFF_BL + nl * ROWB + kq * 16) = lo;
        }
        __syncthreads();

#pragma unroll
        for (int kt = 0; kt < 2; kt++) {
            uint32_t ah[4][4], al[4][4], bh[4][2], bl[4][2];
#pragma unroll
            for (int mi = 0; mi < 4; mi++) {
                uint32_t off = aBase + (uint32_t)(mi * 16) * ROWB + kt * 32;
                ldsm4(ah[mi][0], ah[mi][1], ah[mi][2], ah[mi][3], sb + OFF_AH + off);
                ldsm4(al[mi][0], al[mi][1], al[mi][2], al[mi][3], sb + OFF_AL + off);
            }
#pragma unroll
            for (int np = 0; np < 2; np++) {
                uint32_t off = bBase + (uint32_t)(np * 16) * ROWB + kt * 32;
                ldsm4(bh[np * 2][0], bh[np * 2][1], bh[np * 2 + 1][0], bh[np * 2 + 1][1],
                      sb + OFF_BH + off);
                ldsm4(bl[np * 2][0], bl[np * 2][1], bl[np * 2 + 1][0], bl[np * 2 + 1][1],
                      sb + OFF_BL + off);
            }
#pragma unroll
            for (int mi = 0; mi < 4; mi++)
#pragma unroll
                for (int ni = 0; ni < 4; ni++) {
                    MMA_BF16(c[mi][ni], ah[mi], bh[ni]);
                    MMA_BF16(c[mi][ni], ah[mi], bl[ni]);
                    MMA_BF16(c[mi][ni], al[mi], bh[ni]);
                }
        }
        __syncthreads();
    }

    // ---- epilogue ----
    int g = lane >> 2, t4 = lane & 3;
#pragma unroll
    for (int mi = 0; mi < 4; mi++) {
#pragma unroll
        for (int ni = 0; ni < 4; ni++) {
            int m = m0 + warp_m * 64 + mi * 16 + g;
            int n = n0 + warp_n * 32 + ni * 8 + t4 * 2;
            if (m < M)
                *(float2*)(C + (size_t)m * HDIM + n) = make_float2(c[mi][ni][0], c[mi][ni][1]);
            if (m + 8 < M)
                *(float2*)(C + (size_t)(m + 8) * HDIM + n) = make_float2(c[mi][ni][2], c[mi][ni][3]);
        }
    }
}

// ---------------- per-node attention scalars ----------------
__global__ void k_attvec(const float* __restrict__ h, const float* __restrict__ vs,
                         const float* __restrict__ vd) {
    int n = blockIdx.x, t = threadIdx.x;
    __shared__ float r1[256], r2[256];
    float v = h[(size_t)n * HDIM + t];
    r1[t] = v * vs[t];
    r2[t] = v * vd[t];
    __syncthreads();
    for (int off = 128; off > 0; off >>= 1) {
        if (t < off) { r1[t] += r1[t + off]; r2[t] += r2[t + off]; }
        __syncthreads();
    }
    if (t == 0) { g_asrc[n] = r1[0]; g_adst[n] = r2[0]; }
}

// ---------------- edge softmax + aggregation ----------------
__global__ void k_agg(const float* __restrict__ hin, const float* __restrict__ bias,
                      float* __restrict__ hout) {
    int n = blockIdx.x, t = threadIdx.x;
    int begin = g_rowptr[n], end = g_rowptr[n + 1];
    float ad = g_adst[n];
    __shared__ float sw[256];
    __shared__ int   ss[256];
    __shared__ float red[256];

    float m = -1e30f;
    for (int e = begin + t; e < end; e += 256) {
        float v = g_asrc[g_csrc[e]] + ad;
        v = v > 0.f ? v : NEG_SLOPE * v;
        m = fmaxf(m, v);
    }
    red[t] = m; __syncthreads();
    for (int off = 128; off > 0; off >>= 1) {
        if (t < off) red[t] = fmaxf(red[t], red[t + off]);
        __syncthreads();
    }
    m = red[0];
    __syncthreads();

    float acc = 0.f, lsum = 0.f;
    for (int cs = begin; cs < end; cs += 256) {
        int cnt = min(256, end - cs);
        if (t < cnt) {
            int s = g_csrc[cs + t];
            float v = g_asrc[s] + ad;
            v = v > 0.f ? v : NEG_SLOPE * v;
            float w = expf(v - m);
            sw[t] = w; ss[t] = s; lsum += w;
        }
        __syncthreads();
        for (int j = 0; j < cnt; j++)
            acc += sw[j] * hin[(size_t)ss[j] * HDIM + t];
        __syncthreads();
    }
    red[t] = lsum; __syncthreads();
    for (int off = 128; off > 0; off >>= 1) {
        if (t < off) red[t] += red[t + off];
        __syncthreads();
    }
    float S = red[0];
    float o = acc / (S + EPS) + bias[t];
    hout[(size_t)n * HDIM + t] = fmaxf(o, 0.f);
}

// ---------------- global attention ----------------
__global__ void k_gate(const float* __restrict__ h, const float* __restrict__ gw,
                       const float* __restrict__ gb) {
    int n = blockIdx.x, t = threadIdx.x;
    __shared__ float r[256];
    r[t] = h[(size_t)n * HDIM + t] * gw[t];
    __syncthreads();
    for (int off = 128; off > 0; off >>= 1) {
        if (t < off) r[t] += r[t + off];
        __syncthreads();
    }
    if (t == 0) g_gate[n] = r[0] + gb[0];
}
__global__ void k_softmax_stats(int N) {
    __shared__ float red[1024];
    int t = threadIdx.x;
    float m = -1e30f;
    for (int i = t; i < N; i += 1024) m = fmaxf(m, g_gate[i]);
    red[t] = m; __syncthreads();
    for (int off = 512; off > 0; off >>= 1) {
        if (t < off) red[t] = fmaxf(red[t], red[t + off]);
        __syncthreads();
    }
    m = red[0];
    __syncthreads();
    float s = 0.f;
    for (int i = t; i < N; i += 1024) s += expf(g_gate[i] - m);
    red[t] = s; __syncthreads();
    for (int off = 512; off > 0; off >>= 1) {
        if (t < off) red[t] += red[t + off];
        __syncthreads();
    }
    if (t == 0) { g_stats[0] = m; g_stats[1] = red[0]; }
}
__global__ void k_ga_partial(const float* __restrict__ h, int N) {
    int b = blockIdx.x, t = threadIdx.x;
    float m = g_stats[0], S = g_stats[1];
    float acc = 0.f;
    for (int n = b; n < N; n += 256)
        acc += (expf(g_gate[n] - m) / S) * h[(size_t)n * HDIM + t];
    g_partial[b * 256 + t] = acc;
}
__global__ void k_ga_final(float* __restrict__ out) {
    int t = threadIdx.x;
    float acc = 0.f;
    for (int b = 0; b < 256; b++) acc += g_partial[b * 256 + t];
    out[t] = acc;
}

// ---------------- launch ----------------
extern "C" void kernel_launch(void* const* d_in, const int* in_sizes, int n_in,
                              void* d_out, int out_size) {
    const float* x   = (const float*)d_in[0];
    const int*   ei  = (const int*)d_in[1];
    const float* W1  = (const float*)d_in[2];
    const float* b1  = (const float*)d_in[3];
    const float* as1 = (const float*)d_in[4];
    const float* ad1 = (const float*)d_in[5];
    const float* W2  = (const float*)d_in[6];
    const float* b2  = (const float*)d_in[7];
    const float* as2 = (const float*)d_in[8];
    const float* ad2 = (const float*)d_in[9];
    const float* gw  = (const float*)d_in[10];
    const float* gb  = (const float*)d_in[11];
    float*       out = (float*)d_out;

    const int D = 768;
    const int N = in_sizes[0] / D;
    const int E = in_sizes[1] / 2;

    float *bufA, *bufB, *wt;
    cudaGetSymbolAddress((void**)&bufA, g_bufA);
    cudaGetSymbolAddress((void**)&bufB, g_bufB);
    cudaGetSymbolAddress((void**)&wt,   g_WT);

    // CSR build
    k_init_counts<<<(N + 255) / 256, 256>>>(N);
    k_hist<<<(E + 255) / 256, 256>>>(ei, E);
    k_scan<<<1, 1024>>>(N);
    k_scatter<<<(N + E + 255) / 256, 256>>>(ei, N, E);

    dim3 gg((N + 127) / 128, 2);

    // layer 1
    k_transpose<<<dim3(HDIM / 32, D / 32), dim3(32, 8)>>>(W1, wt, D, HDIM);
    k_gemm_bf16<<<gg, 256>>>(x, wt, bufA, N, D);
    k_attvec<<<N, 256>>>(bufA, as1, ad1);
    k_agg<<<N, 256>>>(bufA, b1, bufB);

    // layer 2
    k_transpose<<<dim3(HDIM / 32, HDIM / 32), dim3(32, 8)>>>(W2, wt, HDIM, HDIM);
    k_gemm_bf16<<<gg, 256>>>(bufB, wt, bufA, N, HDIM);
    k_attvec<<<N, 256>>>(bufA, as2, ad2);
    k_agg<<<N, 256>>>(bufA, b2, bufB);

    // global attention
    k_gate<<<N, 256>>>(bufB, gw, gb);
    k_softmax_stats<<<1, 1024>>>(N);
    k_ga_partial<<<256, 256>>>(bufB, N);
    k_ga_final<<<1, 256>>>(out);
}